// round 10
// baseline (speedup 1.0000x reference)
#include <cuda_runtime.h>

// Problem constants
#define NB 4
#define NN 8192
#define MCHUNK 512             // m's per chunk (SMEM tile)
#define NCH (NN / MCHUNK)      // 16 m-chunks
#define THREADS 128
#define QPT 4                  // queries per thread
#define QBLK (THREADS * QPT)   // 512 queries per CTA
#define NQB (NN / QBLK)        // 16 query blocks

// Per-(batch, m-chunk, query) partials: {sum_e, ax, ay, az}. 4*16*8192*16B = 8MB (L2-resident).
__device__ float4 g_partial[NB * NCH * NN];
// Completion counters, one per (batch, query-block). Zero-init at load; the
// reducing CTA resets its counter to 0 so every graph replay starts clean.
__device__ int g_cnt[NB * NQB];

// ---------- f32x2 helpers (sm_103a packed fp32) ----------
__device__ __forceinline__ unsigned long long pack2(float lo, float hi) {
    unsigned long long r;
    asm("mov.b64 %0, {%1, %2};" : "=l"(r) : "f"(lo), "f"(hi));
    return r;
}
__device__ __forceinline__ void unpack2(unsigned long long v, float& lo, float& hi) {
    asm("mov.b64 {%0, %1}, %2;" : "=f"(lo), "=f"(hi) : "l"(v));
}
__device__ __forceinline__ unsigned long long fma2(unsigned long long a, unsigned long long b,
                                                   unsigned long long c) {
    unsigned long long r;
    asm("fma.rn.f32x2 %0, %1, %2, %3;" : "=l"(r) : "l"(a), "l"(b), "l"(c));
    return r;
}
__device__ __forceinline__ unsigned long long mul2(unsigned long long a, unsigned long long b) {
    unsigned long long r;
    asm("mul.rn.f32x2 %0, %1, %2;" : "=l"(r) : "l"(a), "l"(b));
    return r;
}
__device__ __forceinline__ unsigned long long add2(unsigned long long a, unsigned long long b) {
    unsigned long long r;
    asm("add.rn.f32x2 %0, %1, %2;" : "=l"(r) : "l"(a), "l"(b));
    return r;
}
__device__ __forceinline__ float ex2f(float x) {
    float r;
    asm("ex2.approx.ftz.f32 %0, %1;" : "=f"(r) : "f"(x));
    return r;
}

// log2(e) / sqrt(3): folds the attention scale and the exp->ex2 conversion into q.
#define QFOLD 0.8329433338549414f

// ---------------------------------------------------------------------------
// Fused kernel: per (batch, m-chunk) partial softmax numerators; the LAST
// CTA to finish a (batch, query-block) group (tracked by an atomic counter)
// reduces all NCH chunk partials for its 512 queries, normalizes, adds the
// residual, and writes the final output. This removes the second kernel and
// overlaps the reduction with the partial-CTA tail.
// ---------------------------------------------------------------------------
__global__ __launch_bounds__(THREADS, 5) void attn_fused_kernel(
    const float* __restrict__ X,   // (B, N, 3)
    const float* __restrict__ W,   // (9, 3) row-major
    const float* __restrict__ Bq,  // (9,)
    float* __restrict__ O)         // (B, N, 3)
{
    // Pair-interleaved SMEM, per pair p (m = 2p, 2p+1), 12 floats:
    //   [kx0 kx1 ky0 ky1 | kz0 kz1 vx0 vx1 | vy0 vy1 vz0 vz1]
    // -> each b64 half of a ulonglong2 load IS a packed f32x2 operand.
    __shared__ __align__(16) float skv[MCHUNK * 6];   // 12 KB
    __shared__ int s_last;

    const int ch  = blockIdx.x;   // m-chunk
    const int qb  = blockIdx.y;   // query block
    const int b   = blockIdx.z;   // batch
    const int tid = threadIdx.x;

    const float* xb = X + (size_t)b * NN * 3;

    // ---- Fill SMEM: project k,v for this m-chunk (4 m's per thread) ----
    #pragma unroll
    for (int i = 0; i < MCHUNK; i += THREADS) {
        const int ml = i + tid;
        const int m  = ch * MCHUNK + ml;
        const float x0 = xb[m * 3 + 0];
        const float x1 = xb[m * 3 + 1];
        const float x2 = xb[m * 3 + 2];
        const int p = ml >> 1, h = ml & 1;
        float* base = skv + 12 * p + h;
        #pragma unroll
        for (int j = 0; j < 3; j++) {
            // k_j = qkv column 3j+1, v_j = column 3j+2
            const int ck = (3 * j + 1) * 3;
            const int cv = (3 * j + 2) * 3;
            float kj = W[ck + 0] * x0 + W[ck + 1] * x1 + W[ck + 2] * x2 + Bq[3 * j + 1];
            float vj = W[cv + 0] * x0 + W[cv + 1] * x1 + W[cv + 2] * x2 + Bq[3 * j + 2];
            base[2 * j]     = kj;   // offsets 0,2,4 (+h)
            base[6 + 2 * j] = vj;   // offsets 6,8,10 (+h)
        }
    }
    __syncthreads();

    // ---- This thread's four queries, pre-scaled by log2(e)/sqrt(3) ----
    unsigned long long qx[QPT], qy[QPT], qz[QPT];
    unsigned long long sum[QPT], ax[QPT], ay[QPT], az[QPT];

    #pragma unroll
    for (int q = 0; q < QPT; q++) {
        const int n = qb * QBLK + q * THREADS + tid;
        const float x0 = xb[n * 3 + 0], x1 = xb[n * 3 + 1], x2 = xb[n * 3 + 2];
        const float q0 = (W[0]  * x0 + W[1]  * x1 + W[2]  * x2 + Bq[0]) * QFOLD;
        const float q1 = (W[9]  * x0 + W[10] * x1 + W[11] * x2 + Bq[3]) * QFOLD;
        const float q2 = (W[18] * x0 + W[19] * x1 + W[20] * x2 + Bq[6]) * QFOLD;
        qx[q] = pack2(q0, q0);
        qy[q] = pack2(q1, q1);
        qz[q] = pack2(q2, q2);
        sum[q] = 0ULL; ax[q] = 0ULL; ay[q] = 0ULL; az[q] = 0ULL;
    }

    const ulonglong2* kv2 = reinterpret_cast<const ulonglong2*>(skv);

    #pragma unroll 2
    for (int p = 0; p < MCHUNK / 2; p++) {
        ulonglong2 A  = kv2[3 * p + 0];   // .x={kx0,kx1} .y={ky0,ky1}
        ulonglong2 Bv = kv2[3 * p + 1];   // .x={kz0,kz1} .y={vx0,vx1}
        ulonglong2 C  = kv2[3 * p + 2];   // .x={vy0,vy1} .y={vz0,vz1}

        #pragma unroll
        for (int q = 0; q < QPT; q++) {
            // score for both m's (already in log2 domain)
            unsigned long long s2 = fma2(qx[q], A.x, fma2(qy[q], A.y, mul2(qz[q], Bv.x)));
            float s0, s1;
            unpack2(s2, s0, s1);
            unsigned long long e2 = pack2(ex2f(s0), ex2f(s1));

            sum[q] = add2(sum[q], e2);
            ax[q]  = fma2(e2, Bv.y, ax[q]);
            ay[q]  = fma2(e2, C.x,  ay[q]);
            az[q]  = fma2(e2, C.y,  az[q]);
        }
    }

    // ---- Horizontal-reduce packed lanes; keep own partials in registers ----
    float4 mine[QPT];
    const size_t pbase = (size_t)(b * NCH + ch) * NN;
    #pragma unroll
    for (int q = 0; q < QPT; q++) {
        const int n = qb * QBLK + q * THREADS + tid;
        float s0, s1, x0, x1, y0, y1, z0, z1;
        unpack2(sum[q], s0, s1); unpack2(ax[q], x0, x1);
        unpack2(ay[q], y0, y1);  unpack2(az[q], z0, z1);
        float4 r; r.x = s0 + s1; r.y = x0 + x1; r.z = y0 + y1; r.w = z0 + z1;
        mine[q] = r;
        g_partial[pbase + n] = r;
    }

    // ---- Completion protocol: last CTA of this (b, qb) group reduces ----
    __threadfence();   // make partial stores visible device-wide before count
    if (tid == 0) {
        int old = atomicAdd(&g_cnt[b * NQB + qb], 1);
        s_last = (old == NCH - 1);
        if (s_last) g_cnt[b * NQB + qb] = 0;   // reset for next replay
    }
    __syncthreads();
    if (!s_last) return;

    // ---- Final reduction for the 512 queries of (b, qb) ----
    // Thread t owns the same queries it computed: n = qb*QBLK + q*THREADS + t.
    // Sum over chunks in fixed order c=0..NCH-1 (deterministic); use the
    // register-resident value for our own chunk instead of re-reading it.
    #pragma unroll
    for (int q = 0; q < QPT; q++) {
        const int n = qb * QBLK + q * THREADS + tid;
        const float4* pc = g_partial + (size_t)b * NCH * NN + n;

        float s = 0.f, a0 = 0.f, a1 = 0.f, a2 = 0.f;
        #pragma unroll
        for (int c = 0; c < NCH; c++) {
            float4 r = (c == ch) ? mine[q] : pc[(size_t)c * NN];
            s  += r.x;
            a0 += r.y;
            a1 += r.z;
            a2 += r.w;
        }
        const float inv = __fdividef(1.0f, s);
        const size_t o = ((size_t)b * NN + n) * 3;
        O[o + 0] = a0 * inv + xb[n * 3 + 0];
        O[o + 1] = a1 * inv + xb[n * 3 + 1];
        O[o + 2] = a2 * inv + xb[n * 3 + 2];
    }
}

extern "C" void kernel_launch(void* const* d_in, const int* in_sizes, int n_in,
                              void* d_out, int out_size) {
    const float* X  = (const float*)d_in[0];  // pixel_features (4, 8192, 3)
    const float* W  = (const float*)d_in[1];  // W_qkv (9, 3)
    const float* Bq = (const float*)d_in[2];  // b_qkv (9,)
    float* O = (float*)d_out;

    dim3 grid(NCH, NQB, NB);   // (16, 16, 4) = 1024 CTAs
    attn_fused_kernel<<<grid, THREADS>>>(X, W, Bq, O);
}